// round 3
// baseline (speedup 1.0000x reference)
#include <cuda_runtime.h>
#include <math_constants.h>

// ---------------- problem constants ----------------
#define NB 32          // batch
#define NG 20          // gt boxes per image
#define NN 10647       // total anchors: 3*(169+676+2704)
#define NSC0 507       // 3*169
#define NSC1 2535      // 507 + 3*676
#define CH 1024        // IoU chunk size
#define NCHUNK 11      // ceil(10647/1024)

// floor(anchor / sf) * sf, precomputed (exact: small int * power of 2)
__constant__ float c_awsf[9] = {96.f,128.f,352.f, 16.f,48.f,48.f, 8.f,16.f,32.f};
__constant__ float c_ahsf[9] = {64.f,192.f,320.f, 48.f,32.f,112.f, 8.f,24.f,16.f};

// ---------------- scratch (device globals; no allocs) ----------------
__device__ float4 g_box[NB * NN];   // px, py, px+pw, py+ph
__device__ float2 g_al [NB * NN];   // pw*ph, log(1-conf+1e-9)

struct __align__(16) Part { float iou; int idx; float nsum; float ncnt; };
__device__ Part  g_part[NB * NG * NCHUNK];
__device__ float g_terms[NB * NG];

__device__ __forceinline__ float sigmoidf(float x) {
    return 1.0f / (1.0f + expf(-x));
}

struct Loc { int s, W, W2, a, y, x; float sf; };
__device__ __forceinline__ Loc locate(int n) {
    Loc l;
    if (n < NSC0) {
        l.s = 0; l.W = 13; l.W2 = 169; l.sf = 32.f;
        l.a = n / 169; int r = n - l.a * 169; l.y = r / 13; l.x = r - l.y * 13;
    } else if (n < NSC1) {
        int m = n - NSC0;
        l.s = 1; l.W = 26; l.W2 = 676; l.sf = 16.f;
        l.a = m / 676; int r = m - l.a * 676; l.y = r / 26; l.x = r - l.y * 26;
    } else {
        int m = n - NSC1;
        l.s = 2; l.W = 52; l.W2 = 2704; l.sf = 8.f;
        l.a = m / 2704; int r = m - l.a * 2704; l.y = r / 52; l.x = r - l.y * 52;
    }
    return l;
}

// ---------------- K1: decode 340,704 anchors ----------------
__global__ void decode_kernel(const float* __restrict__ x0,
                              const float* __restrict__ x1,
                              const float* __restrict__ x2) {
    int n = blockIdx.x * blockDim.x + threadIdx.x;
    int b = blockIdx.y;
    if (n >= NN) return;
    Loc l = locate(n);
    const float* src = (l.s == 0) ? x0 : (l.s == 1) ? x1 : x2;
    const float* p = src + (size_t)(b * 255 + l.a * 85) * l.W2 + l.y * l.W + l.x;
    float t0 = p[0];
    float t1 = p[l.W2];
    float t2 = p[2 * l.W2];
    float t3 = p[3 * l.W2];
    float t4 = p[4 * l.W2];

    float px = (sigmoidf(t0) + (float)l.x) * l.sf;
    float py = (sigmoidf(t1) + (float)l.y) * l.sf;
    float pw = expf(t2) * c_awsf[l.s * 3 + l.a];
    float ph = expf(t3) * c_ahsf[l.s * 3 + l.a];
    float conf = sigmoidf(t4);

    int i = b * NN + n;
    g_box[i] = make_float4(px, py, px + pw, py + ph);
    g_al[i]  = make_float2(pw * ph, logf(1.0f - conf + 1e-9f));
}

// ---------------- K2: IoU argmax + noobj partials ----------------
// grid = (NCHUNK, NB), block = 640 threads (20 warps; warp w handles gt w)
__global__ void iou_kernel(const float* __restrict__ by) {
    __shared__ float4 sbox[CH];
    __shared__ float2 sal[CH];
    int b = blockIdx.y, chunk = blockIdx.x;
    int n0 = chunk * CH;
    int cnt = min(CH, NN - n0);

    const float4* bb = g_box + b * NN + n0;
    const float2* aa = g_al  + b * NN + n0;
    for (int i = threadIdx.x; i < cnt; i += blockDim.x) {
        sbox[i] = bb[i];
        sal[i]  = aa[i];
    }
    __syncthreads();

    int g = threadIdx.x >> 5;
    int lane = threadIdx.x & 31;
    const float* gt = by + (b * NG + g) * 5;
    float gxl = gt[0], gyt = gt[1], gw = gt[2], gh = gt[3];
    float gxr = gxl + gw, gyb = gyt + gh, garea = gw * gh;

    float bi = -CUDART_INF_F; int bidx = 0x7fffffff;
    float ns = 0.f, nc = 0.f;

    for (int i = lane; i < cnt; i += 32) {
        float4 pb = sbox[i];
        float2 pa = sal[i];
        float xl = fmaxf(pb.x, gxl), yt = fmaxf(pb.y, gyt);
        float xr = fminf(pb.z, gxr), yb = fminf(pb.w, gyb);
        float inter = fmaxf(xr - xl, 0.f) * fmaxf(yb - yt, 0.f);
        float iou = __fdiv_rn(inter, pa.x + garea - inter);
        int gi = n0 + i;
        if (iou > bi || (iou == bi && gi < bidx)) { bi = iou; bidx = gi; }
        if (iou < 0.5f) { ns += pa.y; nc += 1.f; }
    }

    // warp reduce (argmax with first-index tiebreak, sums)
    #pragma unroll
    for (int off = 16; off; off >>= 1) {
        float oi   = __shfl_down_sync(0xffffffffu, bi,   off);
        int   oidx = __shfl_down_sync(0xffffffffu, bidx, off);
        float ons  = __shfl_down_sync(0xffffffffu, ns,   off);
        float onc  = __shfl_down_sync(0xffffffffu, nc,   off);
        if (oi > bi || (oi == bi && oidx < bidx)) { bi = oi; bidx = oidx; }
        ns += ons; nc += onc;
    }
    if (lane == 0) {
        Part p; p.iou = bi; p.idx = bidx; p.nsum = ns; p.ncnt = nc;
        g_part[(b * NG + g) * NCHUNK + chunk] = p;
    }
}

// ---------------- K3: per-(b,g) loss term ----------------
// grid = 640, block = 128
__global__ void finalize_kernel(const float* __restrict__ x0,
                                const float* __restrict__ x1,
                                const float* __restrict__ x2,
                                const float* __restrict__ by) {
    int bg = blockIdx.x;
    int b = bg / NG;
    int tid = threadIdx.x;

    __shared__ int   s_pos;
    __shared__ float s_noobj;
    __shared__ float sraw[5];
    __shared__ float scls[80];

    if (tid == 0) {
        float bi = -CUDART_INF_F; int bidx = 0x7fffffff;
        float ns = 0.f, nc = 0.f;
        #pragma unroll
        for (int c = 0; c < NCHUNK; c++) {
            Part p = g_part[bg * NCHUNK + c];
            if (p.iou > bi || (p.iou == bi && p.idx < bidx)) { bi = p.iou; bidx = p.idx; }
            ns += p.nsum; nc += p.ncnt;
        }
        s_pos = bidx;
        s_noobj = ns / fmaxf(nc, 1.f);
    }
    __syncthreads();

    int pos = s_pos;

    // conf + cls use the CORRECT decode layout (they come from `dec`)
    Loc l = locate(pos);
    const float* src = (l.s == 0) ? x0 : (l.s == 1) ? x1 : x2;
    const float* p = src + (size_t)(b * 255 + l.a * 85) * l.W2 + l.y * l.W + l.x;
    if (tid >= 4 && tid < 85) {
        float v = p[tid * l.W2];
        if (tid == 4) sraw[4] = v;
        else scls[tid - 5] = sigmoidf(v);
    }

    // raw[..., :4] uses the reference's SCRAMBLED layout: all scales reshaped
    // with w1=13 -> view (3, 13, 13, D) after transpose, D = 255*W2/507.
    if (tid < 4) {
        int rl, W2, D; const float* sp;
        if (pos < NSC0)      { rl = pos;        W2 = 169;  D = 85;   sp = x0; }
        else if (pos < NSC1) { rl = pos - NSC0; W2 = 676;  D = 340;  sp = x1; }
        else                 { rl = pos - NSC1; W2 = 2704; D = 1360; sp = x2; }
        int t   = rl * 85 + tid;          // flat idx into (3,13,13,D)
        int P   = 169 * D;
        int a   = t / P;   int rem  = t - a * P;
        int i   = rem / (13 * D); int rem2 = rem - i * 13 * D;
        int j   = rem2 / D;       int d    = rem2 - j * D;
        int e   = a * P + d * 169 + i * 13 + j;   // flat offset in (255*W2) slice
        sraw[tid] = sp[(size_t)b * 255 * W2 + e];
    }
    __syncthreads();

    if (tid < 32) {
        float m = -CUDART_INF_F;
        for (int k = tid; k < 80; k += 32) m = fmaxf(m, scls[k]);
        #pragma unroll
        for (int off = 16; off; off >>= 1) m = fmaxf(m, __shfl_down_sync(0xffffffffu, m, off));
        m = __shfl_sync(0xffffffffu, m, 0);
        float s = 0.f;
        for (int k = tid; k < 80; k += 32) s += expf(scls[k] - m);
        #pragma unroll
        for (int off = 16; off; off >>= 1) s += __shfl_down_sync(0xffffffffu, s, off);
        if (tid == 0) {
            float lse = m + logf(s);
            const float* gt = by + bg * 5;
            int label = (int)gt[4];
            float ce = -(scls[label] - lse);
            float mse = 0.f;
            #pragma unroll
            for (int k = 0; k < 4; k++) { float d = sraw[k] - gt[k]; mse += d * d; }
            mse *= 0.25f;
            float conf = sigmoidf(sraw[4]);
            float obj = logf(conf + 1e-9f);
            g_terms[bg] = mse - obj - s_noobj - ce;
        }
    }
}

// ---------------- K4: deterministic fixed-order sum ----------------
__global__ void reduce_kernel(float* __restrict__ out) {
    __shared__ float s[256];
    float acc = 0.f;
    for (int i = threadIdx.x; i < NB * NG; i += 256) acc += g_terms[i];
    s[threadIdx.x] = acc;
    __syncthreads();
    #pragma unroll
    for (int o = 128; o; o >>= 1) {
        if (threadIdx.x < o) s[threadIdx.x] += s[threadIdx.x + o];
        __syncthreads();
    }
    if (threadIdx.x == 0) out[0] = s[0];
}

// ---------------- launch ----------------
extern "C" void kernel_launch(void* const* d_in, const int* in_sizes, int n_in,
                              void* d_out, int out_size) {
    const float *x0 = nullptr, *x1 = nullptr, *x2 = nullptr, *by = nullptr;
    for (int i = 0; i < n_in; i++) {
        int sz = in_sizes[i];
        if      (sz == NB * 255 * 169)  x0 = (const float*)d_in[i];
        else if (sz == NB * 255 * 676)  x1 = (const float*)d_in[i];
        else if (sz == NB * 255 * 2704) x2 = (const float*)d_in[i];
        else if (sz == NB * NG * 5)     by = (const float*)d_in[i];
    }
    float* out = (float*)d_out;

    decode_kernel<<<dim3((NN + 255) / 256, NB), 256>>>(x0, x1, x2);
    iou_kernel<<<dim3(NCHUNK, NB), 640>>>(by);
    finalize_kernel<<<NB * NG, 128>>>(x0, x1, x2, by);
    reduce_kernel<<<1, 256>>>(out);
}